// round 1
// baseline (speedup 1.0000x reference)
#include <cuda_runtime.h>
#include <math.h>

#define BB 32
#define AA 8400
#define GG 40
#define CC 80
#define ROW 85   // 4 bbox + 1 obj + 80 cls

// ---------------- scratch (device globals; no allocation) ----------------
__device__ unsigned long long d_match[BB * AA];   // matching bitmask per anchor (bit g)
__device__ unsigned long long d_inin [BB * AA];   // is_in bitmask per anchor
__device__ int    d_fgidx[BB * AA];               // compact fg list per batch (offset b*AA)
__device__ int    d_inv  [BB * AA];               // anchor -> compact index
__device__ int    d_fgcnt[BB];
__device__ float  d_cost[(size_t)BB * GG * AA];   // [b][g][i], i = compact fg index
__device__ float  d_iou [(size_t)BB * GG * AA];
__device__ double d_acc[6];                       // iou, obj, cls, l1, num_fg

// ---------------- kernel 0: zero scratch ----------------
__global__ void k_zero() {
    int stride = gridDim.x * blockDim.x;
    for (int i = blockIdx.x * blockDim.x + threadIdx.x; i < BB * AA; i += stride) {
        d_match[i] = 0ull;
        if (i < BB) d_fgcnt[i] = 0;
        if (i < 6)  d_acc[i] = 0.0;
    }
}

// ---------------- kernel 1: center-region test + fg compaction ----------------
__global__ void k_isin(const float* __restrict__ labels,
                       const float* __restrict__ xsA,
                       const float* __restrict__ ysA,
                       const float* __restrict__ stA) {
    __shared__ float gx[GG], gy[GG];
    int b = blockIdx.y;
    if (threadIdx.x < GG) {
        const float* L = labels + (b * GG + threadIdx.x) * 5;
        gx[threadIdx.x] = L[1];
        gy[threadIdx.x] = L[2];
    }
    __syncthreads();
    int a = blockIdx.x * blockDim.x + threadIdx.x;
    if (a >= AA) return;
    float s  = stA[a];
    float xc = (xsA[a] + 0.5f) * s;
    float yc = (ysA[a] + 0.5f) * s;
    float r  = 1.5f * s;
    unsigned long long m = 0ull;
#pragma unroll 8
    for (int g = 0; g < GG; g++) {
        float dl = xc - (gx[g] - r);
        float dr = (gx[g] + r) - xc;
        float dt = yc - (gy[g] - r);
        float db = (gy[g] + r) - yc;
        float mn = fminf(fminf(dl, dr), fminf(dt, db));
        if (mn > 0.0f) m |= (1ull << g);
    }
    d_inin[b * AA + a] = m;
    if (m) {
        int i = atomicAdd(&d_fgcnt[b], 1);
        d_fgidx[b * AA + i] = a;
        d_inv[b * AA + a]   = i;
    }
}

// ---------------- kernel 2: cost + iou matrix for fg anchors only ----------------
__global__ void k_cost(const float* __restrict__ outp,
                       const float* __restrict__ labels) {
    __shared__ float gx[GG], gy[GG], gw[GG], gh[GG];
    __shared__ int   gc[GG];
    int b = blockIdx.y;
    if (threadIdx.x < GG) {
        const float* L = labels + (b * GG + threadIdx.x) * 5;
        gc[threadIdx.x] = (int)L[0];
        gx[threadIdx.x] = L[1]; gy[threadIdx.x] = L[2];
        gw[threadIdx.x] = L[3]; gh[threadIdx.x] = L[4];
    }
    __syncthreads();
    int cnt = d_fgcnt[b];
    int i = blockIdx.x * blockDim.x + threadIdx.x;
    if (i >= cnt) return;
    int a = d_fgidx[b * AA + i];
    const float* o = outp + (size_t)(b * AA + a) * ROW;
    float bx = o[0], by = o[1], bw = o[2], bh = o[3], obj = o[4];

    // sum_c log1p(-sqrt(cls_c * obj))
    float suml = 0.0f;
#pragma unroll 8
    for (int c = 0; c < CC; c++) {
        float p = sqrtf(o[5 + c] * obj);
        suml += log1pf(-p);
    }

    float areap = bw * bh;
    float px1 = bx - bw * 0.5f, py1 = by - bh * 0.5f;
    float px2 = bx + bw * 0.5f, py2 = by + bh * 0.5f;
    unsigned long long inin = d_inin[b * AA + a];

    for (int g = 0; g < GG; g++) {
        float p = sqrtf(o[5 + gc[g]] * obj);
        float delta = logf(p) - log1pf(-p);          // logp - log1mp at the gt class
        float hw = gw[g] * 0.5f, hh = gh[g] * 0.5f;
        float tlx = fmaxf(px1, gx[g] - hw), tly = fmaxf(py1, gy[g] - hh);
        float brx = fminf(px2, gx[g] + hw), bry = fminf(py2, gy[g] + hh);
        float inter = (tlx < brx && tly < bry) ? (brx - tlx) * (bry - tly) : 0.0f;
        float iou = inter / (areap + gw[g] * gh[g] - inter);
        float cost = -suml - delta + 3.0f * (-logf(iou + 1e-8f));
        if (!((inin >> g) & 1ull)) cost += 1e6f;
        size_t off = (size_t)(b * GG + g) * AA + i;
        d_cost[off] = cost;
        d_iou[off]  = iou;
    }
}

// ---------------- kernel 3: per-(b,g) dynamic_k + stable top-k selection ----------------
__global__ void k_select() {
    int b = blockIdx.y, g = blockIdx.x;
    int N = d_fgcnt[b];
    const float* iouR = d_iou  + (size_t)(b * GG + g) * AA;
    const float* cstR = d_cost + (size_t)(b * GG + g) * AA;
    __shared__ unsigned long long s[128];
    int tid = threadIdx.x;

    // phase A: sum of top-10 ious (iou >= 0 so raw bits are order-preserving)
    float sum = 0.0f;
    unsigned long long prev = 0xFFFFFFFFFFFFFFFFull;
    for (int t = 0; t < 10; t++) {
        unsigned long long best = 0ull;
        for (int i = tid; i < N; i += 128) {
            unsigned long long key =
                ((unsigned long long)__float_as_uint(iouR[i]) << 32) | (unsigned)i;
            if (key < prev && key > best) best = key;
        }
        s[tid] = best; __syncthreads();
        for (int o = 64; o > 0; o >>= 1) {
            if (tid < o && s[tid + o] > s[tid]) s[tid] = s[tid + o];
            __syncthreads();
        }
        unsigned long long mx = s[0]; __syncthreads();
        prev = mx;
        sum += __uint_as_float((unsigned)(mx >> 32));
    }
    int k = (int)sum;           // f32 truncation, like .astype(int32)
    if (k < 1) k = 1;

    // phase B: select k smallest (cost, anchor-index) — stable argsort semantics
    prev = 0ull;
    for (int t = 0; t < k; t++) {
        unsigned long long best = 0xFFFFFFFFFFFFFFFFull;
        for (int i = tid; i < N; i += 128) {
            unsigned cb = __float_as_uint(cstR[i]);
            cb = (cb & 0x80000000u) ? ~cb : (cb | 0x80000000u);   // total order map
            unsigned long long key = ((unsigned long long)cb << 32) | (unsigned)i;
            if (key > prev && key < best) best = key;
        }
        s[tid] = best; __syncthreads();
        for (int o = 64; o > 0; o >>= 1) {
            if (tid < o && s[tid + o] < s[tid]) s[tid] = s[tid + o];
            __syncthreads();
        }
        unsigned long long mn = s[0]; __syncthreads();
        if (mn == 0xFFFFFFFFFFFFFFFFull) break;
        prev = mn;
        if (tid == 0) {
            int i = (int)(unsigned)(mn & 0xFFFFFFFFull);
            int a = d_fgidx[b * AA + i];
            atomicOr(&d_match[b * AA + a], 1ull << g);
        }
    }
}

// ---------------- kernel 4: multi-resolution + loss accumulation ----------------
__device__ __forceinline__ float blockSum(float v, float* s) {
    int tid = threadIdx.x;
    s[tid] = v; __syncthreads();
    for (int o = blockDim.x >> 1; o > 0; o >>= 1) {
        if (tid < o) s[tid] += s[tid + o];
        __syncthreads();
    }
    float r = s[0]; __syncthreads();
    return r;
}

__global__ void k_loss(const float* __restrict__ outp,
                       const float* __restrict__ orig,
                       const float* __restrict__ labels,
                       const float* __restrict__ xsA,
                       const float* __restrict__ ysA,
                       const float* __restrict__ stA) {
    __shared__ float s[256];
    int b = blockIdx.y;
    int a = blockIdx.x * blockDim.x + threadIdx.x;
    float v_obj = 0.f, v_iou = 0.f, v_cls = 0.f, v_l1 = 0.f, v_fg = 0.f;
    if (a < AA) {
        const float* o = outp + (size_t)(b * AA + a) * ROW;
        float x = o[4];
        unsigned long long m = d_match[b * AA + a];
        float fg = m ? 1.0f : 0.0f;
        v_obj = fmaxf(x, 0.0f) - x * fg + log1pf(expf(-fabsf(x)));
        if (m) {
            v_fg = 1.0f;
            int i = d_inv[b * AA + a];
            int mg;
            if (__popcll(m) > 1) {
                // best_gt = argmin over g of cost (first index wins, like jnp.argmin)
                float best = 3.4e38f; mg = 0;
                for (int g = 0; g < GG; g++) {
                    float c = d_cost[(size_t)(b * GG + g) * AA + i];
                    if (c < best) { best = c; mg = g; }
                }
            } else {
                mg = __ffsll((long long)m) - 1;
            }
            float pred_iou = d_iou[(size_t)(b * GG + mg) * AA + i];
            const float* L = labels + (b * GG + mg) * 5;
            int   mc = (int)L[0];
            float gx = L[1], gy = L[2], gw = L[3], gh = L[4];

            // iou_elem(pred, target)
            float bx = o[0], by = o[1], bw = o[2], bh = o[3];
            float tlx = fmaxf(bx - bw * 0.5f, gx - gw * 0.5f);
            float tly = fmaxf(by - bh * 0.5f, gy - gh * 0.5f);
            float brx = fminf(bx + bw * 0.5f, gx + gw * 0.5f);
            float bry = fminf(by + bh * 0.5f, gy + gh * 0.5f);
            float inter = (tlx < brx && tly < bry) ? (brx - tlx) * (bry - tly) : 0.0f;
            float iou = inter / (bw * bh + gw * gh - inter + 1e-16f);
            v_iou = 1.0f - iou * iou;

            // cls BCE: target = one_hot(mc) * pred_iou
            float cl = 0.0f;
#pragma unroll 8
            for (int c = 0; c < CC; c++) {
                float xl = o[5 + c];
                float t  = (c == mc) ? pred_iou : 0.0f;
                cl += fmaxf(xl, 0.0f) - xl * t + log1pf(expf(-fabsf(xl)));
            }
            v_cls = cl;

            // l1
            float st = stA[a], xsh = xsA[a], ysh = ysA[a];
            float t0 = gx / st - xsh;
            float t1 = gy / st - ysh;
            float t2 = logf(gw / st + 1e-8f);
            float t3 = logf(gh / st + 1e-8f);
            const float* op = orig + (size_t)(b * AA + a) * 4;
            v_l1 = fabsf(op[0] - t0) + fabsf(op[1] - t1) +
                   fabsf(op[2] - t2) + fabsf(op[3] - t3);
        }
    }
    float r;
    r = blockSum(v_iou, s); if (threadIdx.x == 0) atomicAdd(&d_acc[0], (double)r);
    r = blockSum(v_obj, s); if (threadIdx.x == 0) atomicAdd(&d_acc[1], (double)r);
    r = blockSum(v_cls, s); if (threadIdx.x == 0) atomicAdd(&d_acc[2], (double)r);
    r = blockSum(v_l1,  s); if (threadIdx.x == 0) atomicAdd(&d_acc[3], (double)r);
    r = blockSum(v_fg,  s); if (threadIdx.x == 0) atomicAdd(&d_acc[4], (double)r);
}

// ---------------- kernel 5: finalize ----------------
__global__ void k_final(float* out) {
    double nfg = d_acc[4];
    if (nfg < 1.0) nfg = 1.0;
    float liou = (float)(5.0 * d_acc[0] / nfg);   // reg_weight * loss_iou
    float lobj = (float)(d_acc[1] / nfg);
    float lcls = (float)(d_acc[2] / nfg);
    float ll1  = (float)(d_acc[3] / nfg);
    out[0] = liou + lobj + lcls + ll1;
    out[1] = liou;
    out[2] = lobj;
    out[3] = lcls;
    out[4] = ll1;
    out[5] = (float)(d_acc[4] / (double)(BB * GG));
}

// ---------------- launch ----------------
extern "C" void kernel_launch(void* const* d_in, const int* in_sizes, int n_in,
                              void* d_out, int out_size) {
    const float* outputs = (const float*)d_in[0];
    const float* origin  = (const float*)d_in[1];
    const float* labels  = (const float*)d_in[2];
    const float* xs      = (const float*)d_in[3];
    const float* ys      = (const float*)d_in[4];
    const float* st      = (const float*)d_in[5];

    k_zero<<<1056, 256>>>();

    dim3 g1((AA + 255) / 256, BB);
    k_isin<<<g1, 256>>>(labels, xs, ys, st);

    dim3 g2((AA + 127) / 128, BB);
    k_cost<<<g2, 128>>>(outputs, labels);

    dim3 g3(GG, BB);
    k_select<<<g3, 128>>>();

    k_loss<<<g1, 256>>>(outputs, origin, labels, xs, ys, st);

    k_final<<<1, 1>>>((float*)d_out);
}

// round 2
// speedup vs baseline: 1.0932x; 1.0932x over previous
#include <cuda_runtime.h>
#include <math.h>
#include <float.h>

#define BB 32
#define AA 8400
#define GG 40
#define CC 80
#define ROW 85
#define SP 1088      // max candidates per batch (>= 1080 hard bound), row stride
#define MM 512       // max matched anchors per batch (>= 400 hard bound)

// ---------------- scratch (device globals; no allocation) ----------------
__device__ unsigned long long d_match[BB * AA];   // per-anchor match bitmask (bit g)
__device__ unsigned long long d_inin [BB * AA];   // per-anchor in-center-region bitmask
__device__ int    d_fgidx[BB * SP];               // compact candidate list (ascending a)
__device__ int    d_inv  [BB * AA];               // anchor -> compact index
__device__ int    d_fgcnt[BB];
__device__ int    d_mcnt [BB];
__device__ int    d_midx [BB * MM];               // matched anchors per batch
__device__ float  d_cost[(size_t)BB * GG * SP];   // [b][g][i]
__device__ float  d_iou [(size_t)BB * GG * SP];
__device__ double d_acc[6];                       // iou, obj, cls, l1, num_fg

// ---------------- kernel 1: center-region bitmask + init ----------------
__global__ void k_isin(const float* __restrict__ labels,
                       const float* __restrict__ xsA,
                       const float* __restrict__ ysA,
                       const float* __restrict__ stA) {
    __shared__ float gx[GG], gy[GG];
    int b = blockIdx.y;
    if (threadIdx.x < GG) {
        const float* L = labels + (b * GG + threadIdx.x) * 5;
        gx[threadIdx.x] = L[1];
        gy[threadIdx.x] = L[2];
    }
    if (blockIdx.x == 0 && threadIdx.x == 0) d_mcnt[b] = 0;
    if (blockIdx.x == 0 && b == 0 && threadIdx.x < 6) d_acc[threadIdx.x] = 0.0;
    __syncthreads();
    int a = blockIdx.x * blockDim.x + threadIdx.x;
    if (a >= AA) return;
    float s  = stA[a];
    float xc = (xsA[a] + 0.5f) * s;
    float yc = (ysA[a] + 0.5f) * s;
    float r  = 1.5f * s;
    unsigned long long m = 0ull;
#pragma unroll 8
    for (int g = 0; g < GG; g++) {
        float dl = xc - (gx[g] - r);
        float dr = (gx[g] + r) - xc;
        float dt = yc - (gy[g] - r);
        float db = (gy[g] + r) - yc;
        float mn = fminf(fminf(dl, dr), fminf(dt, db));
        if (mn > 0.0f) m |= (1ull << g);
    }
    d_inin [b * AA + a] = m;
    d_match[b * AA + a] = 0ull;
}

// ---------------- kernel 2: ordered compaction (per-batch block scan) ---------
__global__ void k_scan() {
    __shared__ int ssum[256];
    int b = blockIdx.x;
    int tid = threadIdx.x;
    int begin = tid * 33;
    int end   = begin + 33; if (end > AA) end = AA;
    int c = 0;
    for (int a = begin; a < end; a++) c += (d_inin[b * AA + a] != 0ull);
    ssum[tid] = c; __syncthreads();
    for (int o = 1; o < 256; o <<= 1) {
        int v = (tid >= o) ? ssum[tid - o] : 0;
        __syncthreads();
        ssum[tid] += v;
        __syncthreads();
    }
    int pos = ssum[tid] - c;                // exclusive prefix
    if (tid == 255) d_fgcnt[b] = ssum[255];
    for (int a = begin; a < end; a++) {
        if (d_inin[b * AA + a] != 0ull) {
            d_fgidx[b * SP + pos] = a;
            d_inv  [b * AA + a]   = pos;
            pos++;
        }
    }
}

// ---------------- kernel 3: cost + iou for candidates (fast math, gated) -----
__global__ void __launch_bounds__(128) k_cost(const float* __restrict__ outp,
                                              const float* __restrict__ labels) {
    __shared__ float srow[128][87];   // stride 87: conflict-free column reads
    __shared__ float gx[GG], gy[GG], gw[GG], gh[GG];
    __shared__ int   gc[GG];
    int b = blockIdx.y;
    int tid = threadIdx.x;
    if (tid < GG) {
        const float* L = labels + (b * GG + tid) * 5;
        gc[tid] = (int)L[0];
        gx[tid] = L[1]; gy[tid] = L[2];
        gw[tid] = L[3]; gh[tid] = L[4];
    }
    int cnt = d_fgcnt[b];
    int i0  = blockIdx.x * 128;
    // cooperative coalesced staging of 128 rows
    int wid = tid >> 5, lane = tid & 31;
    for (int r = wid; r < 128; r += 4) {
        int i = i0 + r;
        if (i < cnt) {
            const float* src = outp + (size_t)(b * AA + d_fgidx[b * SP + i]) * ROW;
            for (int c2 = lane; c2 < ROW; c2 += 32) srow[r][c2] = src[c2];
        }
    }
    __syncthreads();
    int i = i0 + tid;
    if (i >= cnt) return;
    int a = d_fgidx[b * SP + i];
    const float* o = srow[tid];
    float obj = o[4];

    // suml = sum_c log1p(-sqrt(cls_c*obj))   (fast path: selection-only)
    float suml = 0.0f;
#pragma unroll 8
    for (int c = 0; c < CC; c++) {
        float x = o[5 + c] * obj;
        float p = x * rsqrtf(x);
        suml += __logf(1.0f - p);
    }

    float bx = o[0], by = o[1], bw = o[2], bh = o[3];
    float areap = bw * bh;
    float px1 = bx - bw * 0.5f, py1 = by - bh * 0.5f;
    float px2 = bx + bw * 0.5f, py2 = by + bh * 0.5f;
    unsigned long long inin = d_inin[b * AA + a];

    for (int g = 0; g < GG; g++) {
        float hw = gw[g] * 0.5f, hh = gh[g] * 0.5f;
        float tlx = fmaxf(px1, gx[g] - hw), tly = fmaxf(py1, gy[g] - hh);
        float brx = fminf(px2, gx[g] + hw), bry = fminf(py2, gy[g] + hh);
        float inter = (tlx < brx && tly < bry) ? (brx - tlx) * (bry - tly) : 0.0f;
        float iou = __fdividef(inter, areap + gw[g] * gh[g] - inter);
        size_t off = (size_t)(b * GG + g) * SP + i;
        d_iou[off] = iou;
        float cost = FLT_MAX;                  // out-of-region: never selectable
        if ((inin >> g) & 1ull) {
            float xg = o[5 + gc[g]] * obj;
            float pg = xg * rsqrtf(xg);
            float lp  = 0.5f * __logf(xg);     // log(sqrt(xg))
            float l1m = __logf(1.0f - pg);
            cost = -suml - (lp - l1m) - 3.0f * __logf(iou + 1e-8f);
        }
        d_cost[off] = cost;
    }
}

// ---------------- kernel 4: warp-per-(b,g) dynamic_k + stable top-k ----------
__global__ void __launch_bounds__(128) k_select() {
    int w    = (blockIdx.x * 128 + threadIdx.x) >> 5;   // 0..1279
    int lane = threadIdx.x & 31;
    int b = w / GG, g = w % GG;
    int N = d_fgcnt[b];

    unsigned v[34];
    const float* irow = d_iou + (size_t)w * SP;
#pragma unroll
    for (int j = 0; j < 34; j++) {
        int i = lane + (j << 5);
        v[j] = (i < N) ? __float_as_uint(irow[i]) : 0u;
    }
    // phase A: sum of global top-10 iou values (key = bits<<32 | idx, unique)
    float sum = 0.0f;
    unsigned long long prev = ~0ull;
    for (int t = 0; t < 10; t++) {
        unsigned long long best = 0ull;
#pragma unroll
        for (int j = 0; j < 34; j++) {
            unsigned long long key =
                ((unsigned long long)v[j] << 32) | (unsigned)(lane + (j << 5));
            if (key < prev && key > best) best = key;
        }
        for (int o = 16; o > 0; o >>= 1) {
            unsigned long long other = __shfl_xor_sync(0xffffffffu, best, o);
            if (other > best) best = other;
        }
        prev = best;
        sum += __uint_as_float((unsigned)(best >> 32));
    }
    int k = (int)sum;          // f32 truncation, like .astype(int32)
    if (k < 1)  k = 1;
    if (k > 10) k = 10;

    // phase B: k smallest (cost, idx) keys — stable argsort semantics
    const float* crow = d_cost + (size_t)w * SP;
#pragma unroll
    for (int j = 0; j < 34; j++) {
        int i = lane + (j << 5);
        if (i < N) {
            unsigned cb = __float_as_uint(crow[i]);
            v[j] = (cb & 0x80000000u) ? ~cb : (cb | 0x80000000u);
        } else v[j] = 0xFFFFFFFFu;
    }
    prev = 0ull;
    for (int t = 0; t < k; t++) {
        unsigned long long best = ~0ull;
#pragma unroll
        for (int j = 0; j < 34; j++) {
            unsigned long long key =
                ((unsigned long long)v[j] << 32) | (unsigned)(lane + (j << 5));
            if (key > prev && key < best) best = key;
        }
        for (int o = 16; o > 0; o >>= 1) {
            unsigned long long other = __shfl_xor_sync(0xffffffffu, best, o);
            if (other < best) best = other;
        }
        if (best == ~0ull) break;
        prev = best;
        if (lane == 0) {
            int i = (int)(unsigned)best;
            if (i < N) {
                int a = d_fgidx[b * SP + i];
                atomicOr(&d_match[b * AA + a], 1ull << g);
            }
        }
    }
}

// ---------------- block reduction helper ----------------
__device__ __forceinline__ float blockSum(float v, float* s) {
    int tid = threadIdx.x;
    s[tid] = v; __syncthreads();
    for (int o = blockDim.x >> 1; o > 0; o >>= 1) {
        if (tid < o) s[tid] += s[tid + o];
        __syncthreads();
    }
    float r = s[0]; __syncthreads();
    return r;
}

// ---------------- kernel 5: obj BCE over all anchors + matched compaction ----
__global__ void k_obj(const float* __restrict__ outp) {
    __shared__ float s[256];
    int b = blockIdx.y;
    int a = blockIdx.x * blockDim.x + threadIdx.x;
    float vo = 0.0f, vf = 0.0f;
    if (a < AA) {
        unsigned long long m = d_match[b * AA + a];
        float x = outp[(size_t)(b * AA + a) * ROW + 4];
        float fg = m ? 1.0f : 0.0f;
        vo = fmaxf(x, 0.0f) - x * fg + log1pf(expf(-fabsf(x)));
        if (m) {
            vf = 1.0f;
            int pos = atomicAdd(&d_mcnt[b], 1);
            d_midx[b * MM + pos] = a;
        }
    }
    float r;
    r = blockSum(vo, s); if (threadIdx.x == 0) atomicAdd(&d_acc[1], (double)r);
    r = blockSum(vf, s); if (threadIdx.x == 0) atomicAdd(&d_acc[4], (double)r);
}

// ---------------- kernel 6: heavy losses on matched anchors only -------------
__global__ void __launch_bounds__(128) k_fgloss(const float* __restrict__ outp,
                                                const float* __restrict__ orig,
                                                const float* __restrict__ labels,
                                                const float* __restrict__ xsA,
                                                const float* __restrict__ ysA,
                                                const float* __restrict__ stA) {
    __shared__ float s[128];
    int b = blockIdx.y;
    int j = blockIdx.x * 128 + threadIdx.x;
    float v_iou = 0.0f, v_cls = 0.0f, v_l1 = 0.0f;
    if (j < d_mcnt[b]) {
        int a = d_midx[b * MM + j];
        unsigned long long m = d_match[b * AA + a];
        int i = d_inv[b * AA + a];
        int mg;
        if (__popcll(m) > 1) {
            float best = FLT_MAX; mg = 0;
            for (int g = 0; g < GG; g++) {
                float c = d_cost[(size_t)(b * GG + g) * SP + i];
                if (c < best) { best = c; mg = g; }
            }
        } else {
            mg = __ffsll((long long)m) - 1;
        }
        const float* L = labels + (b * GG + mg) * 5;
        int   mc = (int)L[0];
        float gxv = L[1], gyv = L[2], gwv = L[3], ghv = L[4];

        const float* o = outp + (size_t)(b * AA + a) * ROW;
        float bx = o[0], by = o[1], bw = o[2], bh = o[3];
        float tlx = fmaxf(bx - bw * 0.5f, gxv - gwv * 0.5f);
        float tly = fmaxf(by - bh * 0.5f, gyv - ghv * 0.5f);
        float brx = fminf(bx + bw * 0.5f, gxv + gwv * 0.5f);
        float bry = fminf(by + bh * 0.5f, gyv + ghv * 0.5f);
        float inter = (tlx < brx && tly < bry) ? (brx - tlx) * (bry - tly) : 0.0f;

        // pred_iou: pairwise formula (no eps), recomputed in full precision
        float pred_iou = inter / (bw * bh + gwv * ghv - inter);
        // loss iou: iou_elem formula (with eps)
        float iou = inter / (bw * bh + gwv * ghv - inter + 1e-16f);
        v_iou = 1.0f - iou * iou;

        float cl = 0.0f;
#pragma unroll 8
        for (int c = 0; c < CC; c++) {
            float xl = o[5 + c];
            float t  = (c == mc) ? pred_iou : 0.0f;
            cl += fmaxf(xl, 0.0f) - xl * t + log1pf(expf(-fabsf(xl)));
        }
        v_cls = cl;

        float st = stA[a];
        float t0 = gxv / st - xsA[a];
        float t1 = gyv / st - ysA[a];
        float t2 = logf(gwv / st + 1e-8f);
        float t3 = logf(ghv / st + 1e-8f);
        const float* op = orig + (size_t)(b * AA + a) * 4;
        v_l1 = fabsf(op[0] - t0) + fabsf(op[1] - t1) +
               fabsf(op[2] - t2) + fabsf(op[3] - t3);
    }
    float r;
    r = blockSum(v_iou, s); if (threadIdx.x == 0) atomicAdd(&d_acc[0], (double)r);
    r = blockSum(v_cls, s); if (threadIdx.x == 0) atomicAdd(&d_acc[2], (double)r);
    r = blockSum(v_l1,  s); if (threadIdx.x == 0) atomicAdd(&d_acc[3], (double)r);
}

// ---------------- kernel 7: finalize ----------------
__global__ void k_final(float* out) {
    double nfg = d_acc[4];
    if (nfg < 1.0) nfg = 1.0;
    float liou = (float)(5.0 * d_acc[0] / nfg);
    float lobj = (float)(d_acc[1] / nfg);
    float lcls = (float)(d_acc[2] / nfg);
    float ll1  = (float)(d_acc[3] / nfg);
    out[0] = liou + lobj + lcls + ll1;
    out[1] = liou;
    out[2] = lobj;
    out[3] = lcls;
    out[4] = ll1;
    out[5] = (float)(d_acc[4] / (double)(BB * GG));
}

// ---------------- launch ----------------
extern "C" void kernel_launch(void* const* d_in, const int* in_sizes, int n_in,
                              void* d_out, int out_size) {
    const float* outputs = (const float*)d_in[0];
    const float* origin  = (const float*)d_in[1];
    const float* labels  = (const float*)d_in[2];
    const float* xs      = (const float*)d_in[3];
    const float* ys      = (const float*)d_in[4];
    const float* st      = (const float*)d_in[5];

    dim3 gA((AA + 255) / 256, BB);
    k_isin<<<gA, 256>>>(labels, xs, ys, st);

    k_scan<<<BB, 256>>>();

    dim3 gC((SP + 127) / 128 + ((SP % 128) ? 0 : 0), BB);   // 9 x 32
    k_cost<<<dim3(9, BB), 128>>>(outputs, labels);

    k_select<<<(BB * GG) / 4, 128>>>();

    k_obj<<<gA, 256>>>(outputs);

    k_fgloss<<<dim3(MM / 128, BB), 128>>>(outputs, origin, labels, xs, ys, st);

    k_final<<<1, 1>>>((float*)d_out);
}

// round 3
// speedup vs baseline: 1.1185x; 1.0231x over previous
#include <cuda_runtime.h>
#include <math.h>
#include <float.h>

#define BB 32
#define AA 8400
#define GG 40
#define CC 80
#define ROW 85
#define SP 1536      // max candidates per batch (row stride), N observed ~1080
#define MM 512       // max matched anchors per batch

// ---------------- scratch (device globals; no allocation) ----------------
__device__ unsigned long long d_match[BB * AA];
__device__ unsigned long long d_inin [BB * AA];
__device__ int    d_fgidx[BB * SP];
__device__ int    d_inv  [BB * AA];
__device__ int    d_fgcnt[BB];
__device__ int    d_mcnt [BB];
__device__ int    d_midx [BB * MM];
__device__ float  d_cost[(size_t)BB * GG * SP];
__device__ float  d_iou [(size_t)BB * GG * SP];
__device__ double d_acc[6];

// ---------------- kernel 0: zero bitmasks + counters ----------------
__global__ void k_zero() {
    int stride = gridDim.x * blockDim.x;
    int t0 = blockIdx.x * blockDim.x + threadIdx.x;
    for (int i = t0; i < BB * AA; i += stride) {
        d_inin [i] = 0ull;
        d_match[i] = 0ull;
    }
    if (t0 < BB) d_mcnt[t0] = 0;
    if (t0 < 6)  d_acc[t0] = 0.0;
}

// ---------------- kernel 1: analytic center-region enumeration ----------------
__global__ void k_mark(const float* __restrict__ labels) {
    int t = blockIdx.x * blockDim.x + threadIdx.x;
    if (t >= BB * GG * 3) return;
    int sidx = t % 3;
    int g    = (t / 3) % GG;
    int b    = t / (3 * GG);
    const float* L = labels + (b * GG + g) * 5;
    float gxv = L[1], gyv = L[2];
    float s; int n, base;
    if (sidx == 0)      { s = 8.0f;  n = 80; base = 0;    }
    else if (sidx == 1) { s = 16.0f; n = 40; base = 6400; }
    else                { s = 32.0f; n = 20; base = 8000; }
    float r = 1.5f * s;
    int cx = (int)floorf(gxv / s);
    int cy = (int)floorf(gyv / s);
    for (int dy = -3; dy <= 2; dy++) {
        int ny = cy + dy;
        if (ny < 0 || ny >= n) continue;
        float yc = ((float)ny + 0.5f) * s;
        float dt = yc - (gyv - r);
        float db = (gyv + r) - yc;
        float my = fminf(dt, db);
        if (my <= 0.0f) continue;
        for (int dx = -3; dx <= 2; dx++) {
            int nx = cx + dx;
            if (nx < 0 || nx >= n) continue;
            float xc = ((float)nx + 0.5f) * s;
            float dl = xc - (gxv - r);
            float dr = (gxv + r) - xc;
            if (fminf(fminf(dl, dr), my) > 0.0f)
                atomicOr(&d_inin[b * AA + base + ny * n + nx], 1ull << g);
        }
    }
}

// ---------------- kernel 2: ordered compaction (warp-ballot scan) ----------------
__global__ void k_scan() {
    __shared__ int wcnt[8];
    int b = blockIdx.x;
    int tid = threadIdx.x, wid = tid >> 5, lane = tid & 31;
    const int CH = 1050;                 // 8 warps * 1050 = 8400
    int base = wid * CH;
    int cnt = 0;
    for (int k = 0; k < 33; k++) {
        int a = base + k * 32 + lane;
        bool p = (a < base + CH) && (d_inin[b * AA + a] != 0ull);
        cnt += __popc(__ballot_sync(0xffffffffu, p));
    }
    if (lane == 0) wcnt[wid] = cnt;
    __syncthreads();
    int off = 0;
    for (int w2 = 0; w2 < wid; w2++) off += wcnt[w2];
    if (tid == 0) {
        int tot = 0;
        for (int w2 = 0; w2 < 8; w2++) tot += wcnt[w2];
        d_fgcnt[b] = tot < SP ? tot : SP;
    }
    int pos = off;
    for (int k = 0; k < 33; k++) {
        int a = base + k * 32 + lane;
        bool p = (a < base + CH) && (d_inin[b * AA + a] != 0ull);
        unsigned bal = __ballot_sync(0xffffffffu, p);
        int my = __popc(bal & ((1u << lane) - 1u));
        if (p && pos + my < SP) {
            d_fgidx[b * SP + pos + my] = a;
            d_inv  [b * AA + a]        = pos + my;
        }
        pos += __popc(bal);
    }
}

// ---------------- kernel 3: cost + iou (MUFU-lean) ----------------
__global__ void __launch_bounds__(128) k_cost(const float* __restrict__ outp,
                                              const float* __restrict__ labels) {
    __shared__ float srow[128][87];
    __shared__ float qx1[GG], qy1[GG], qx2[GG], qy2[GG], qar[GG];
    __shared__ int   sgc[GG];
    int b = blockIdx.y;
    int tid = threadIdx.x;
    if (tid < GG) {
        const float* L = labels + (b * GG + tid) * 5;
        float gxv = L[1], gyv = L[2], gwv = L[3], ghv = L[4];
        sgc[tid] = (int)L[0];
        qx1[tid] = gxv - gwv * 0.5f; qx2[tid] = gxv + gwv * 0.5f;
        qy1[tid] = gyv - ghv * 0.5f; qy2[tid] = gyv + ghv * 0.5f;
        qar[tid] = gwv * ghv;
    }
    int cnt = d_fgcnt[b];
    int i0  = blockIdx.x * 128;
    int wid = tid >> 5, lane = tid & 31;
    for (int r = wid; r < 128; r += 4) {
        int i = i0 + r;
        if (i < cnt) {
            const float* src = outp + (size_t)(b * AA + d_fgidx[b * SP + i]) * ROW;
            for (int c2 = lane; c2 < ROW; c2 += 32) srow[r][c2] = src[c2];
        }
    }
    __syncthreads();
    int i = i0 + tid;
    if (i >= cnt) return;
    int a = d_fgidx[b * SP + i];
    const float* o = srow[tid];
    float obj = o[4];

    // suml = sum_c log1p(-sqrt(cls_c*obj)) via 8 group products
    float suml = 0.0f;
#pragma unroll
    for (int grp = 0; grp < 8; grp++) {
        float prod = 1.0f;
#pragma unroll
        for (int c2 = 0; c2 < 10; c2++) {
            float x = o[5 + grp * 10 + c2] * obj;
            prod *= (1.0f - x * rsqrtf(x));
        }
        suml += __logf(prod);
    }

    float bx = o[0], by = o[1], bw = o[2], bh = o[3];
    float areap = bw * bh;
    float px1 = bx - bw * 0.5f, py1 = by - bh * 0.5f;
    float px2 = bx + bw * 0.5f, py2 = by + bh * 0.5f;
    unsigned long long inin = d_inin[b * AA + a];

    for (int g = 0; g < GG; g++) {
        float w = fminf(px2, qx2[g]) - fmaxf(px1, qx1[g]);
        float h = fminf(py2, qy2[g]) - fmaxf(py1, qy1[g]);
        float inter = fmaxf(w, 0.0f) * fmaxf(h, 0.0f);
        float den = areap + qar[g] - inter;
        // FMA-pipe reciprocal (bit-trick + 2 Newton); den >= ~1 always
        float y = __uint_as_float(0x7EF311C3u - __float_as_uint(den));
        y = y * (2.0f - den * y);
        y = y * (2.0f - den * y);
        float iou = inter * y;
        size_t off = (size_t)(b * GG + g) * SP + i;
        d_iou[off] = iou;
        float cost = FLT_MAX;
        if ((inin >> g) & 1ull) {
            float xg = o[5 + sgc[g]] * obj;
            float pg = xg * rsqrtf(xg);
            cost = -suml - (0.5f * __logf(xg) - __logf(1.0f - pg))
                   - 3.0f * __logf(iou + 1e-8f);
        }
        d_cost[off] = cost;
    }
}

// ---------------- kernel 4: block-per-(b,g) dynamic_k + stable top-k ----------
__global__ void __launch_bounds__(256) k_select() {
    __shared__ unsigned long long swp[8];
    __shared__ unsigned long long sbest;
    int bg = blockIdx.x;
    int b  = bg / GG;
    int tid = threadIdx.x, lane = tid & 31, wid = tid >> 5;
    int N = d_fgcnt[b];
    const float* irow = d_iou  + (size_t)bg * SP;
    const float* crow = d_cost + (size_t)bg * SP;

    unsigned kiou[6], kcst[6];
#pragma unroll
    for (int j = 0; j < 6; j++) {
        int i = tid + j * 256;
        bool v = (i < N);
        kiou[j] = v ? __float_as_uint(irow[i]) : 0u;              // iou >= 0
        unsigned cb = v ? __float_as_uint(crow[i]) : 0x7F800000u; // pad +inf
        kcst[j] = (cb & 0x80000000u) ? ~cb : (cb | 0x80000000u);  // order map
    }

    // phase A: sum of top-10 iou values (descending accumulation, like jnp)
    float sum = 0.0f;
    unsigned long long prev = ~0ull;
    for (int t = 0; t < 10; t++) {
        unsigned long long best = 0ull;
#pragma unroll
        for (int j = 0; j < 6; j++) {
            unsigned long long key =
                ((unsigned long long)kiou[j] << 32) | (unsigned)(tid + j * 256);
            if (key < prev && key > best) best = key;
        }
#pragma unroll
        for (int o = 16; o > 0; o >>= 1) {
            unsigned long long oth = __shfl_xor_sync(0xffffffffu, best, o);
            if (oth > best) best = oth;
        }
        if (lane == 0) swp[wid] = best;
        __syncthreads();
        if (tid == 0) {
            unsigned long long m = swp[0];
#pragma unroll
            for (int w2 = 1; w2 < 8; w2++) if (swp[w2] > m) m = swp[w2];
            sbest = m;
        }
        __syncthreads();
        prev = sbest;
        sum += __uint_as_float((unsigned)(prev >> 32));
    }
    int k = (int)sum;
    if (k < 1)  k = 1;
    if (k > 10) k = 10;

    // phase B: k smallest (cost, idx) — stable argsort tie-break by index
    prev = 0ull;
    for (int t = 0; t < k; t++) {
        unsigned long long best = ~0ull;
#pragma unroll
        for (int j = 0; j < 6; j++) {
            unsigned long long key =
                ((unsigned long long)kcst[j] << 32) | (unsigned)(tid + j * 256);
            if (key > prev && key < best) best = key;
        }
#pragma unroll
        for (int o = 16; o > 0; o >>= 1) {
            unsigned long long oth = __shfl_xor_sync(0xffffffffu, best, o);
            if (oth < best) best = oth;
        }
        if (lane == 0) swp[wid] = best;
        __syncthreads();
        if (tid == 0) {
            unsigned long long m = swp[0];
#pragma unroll
            for (int w2 = 1; w2 < 8; w2++) if (swp[w2] < m) m = swp[w2];
            sbest = m;
            int i = (int)(unsigned)(m & 0xFFFFFFFFull);
            if (m != ~0ull && i < N) {
                int g = bg - b * GG;
                int a = d_fgidx[b * SP + i];
                atomicOr(&d_match[b * AA + a], 1ull << g);
            }
        }
        __syncthreads();
        prev = sbest;
    }
}

// ---------------- block reduction helper ----------------
__device__ __forceinline__ float blockSum(float v, float* s) {
    int tid = threadIdx.x;
#pragma unroll
    for (int o = 16; o > 0; o >>= 1) v += __shfl_xor_sync(0xffffffffu, v, o);
    if ((tid & 31) == 0) s[tid >> 5] = v;
    __syncthreads();
    float r = 0.0f;
    if (tid < (blockDim.x >> 5)) r = s[tid];
#pragma unroll
    for (int o = 4; o > 0; o >>= 1) r += __shfl_xor_sync(0xffffffffu, r, o);
    __syncthreads();
    return r;   // valid in thread 0
}

// ---------------- kernel 5: obj BCE over all anchors + matched compaction ----
__global__ void k_obj(const float* __restrict__ outp) {
    __shared__ float s[8];
    int b = blockIdx.y;
    int a = blockIdx.x * blockDim.x + threadIdx.x;
    float vo = 0.0f, vf = 0.0f;
    if (a < AA) {
        unsigned long long m = d_match[b * AA + a];
        float x = outp[(size_t)(b * AA + a) * ROW + 4];
        float fg = m ? 1.0f : 0.0f;
        vo = fmaxf(x, 0.0f) - x * fg + __logf(1.0f + __expf(-fabsf(x)));
        if (m) {
            vf = 1.0f;
            int pos = atomicAdd(&d_mcnt[b], 1);
            if (pos < MM) d_midx[b * MM + pos] = a;
        }
    }
    float r;
    r = blockSum(vo, s); if (threadIdx.x == 0) atomicAdd(&d_acc[1], (double)r);
    r = blockSum(vf, s); if (threadIdx.x == 0) atomicAdd(&d_acc[4], (double)r);
}

// ---------------- kernel 6: heavy losses on matched anchors only -------------
__global__ void __launch_bounds__(128) k_fgloss(const float* __restrict__ outp,
                                                const float* __restrict__ orig,
                                                const float* __restrict__ labels,
                                                const float* __restrict__ xsA,
                                                const float* __restrict__ ysA,
                                                const float* __restrict__ stA) {
    __shared__ float s[8];
    int b = blockIdx.y;
    int j = blockIdx.x * 128 + threadIdx.x;
    float v_iou = 0.0f, v_cls = 0.0f, v_l1 = 0.0f;
    int mc2 = d_mcnt[b]; if (mc2 > MM) mc2 = MM;
    if (j < mc2) {
        int a = d_midx[b * MM + j];
        unsigned long long m = d_match[b * AA + a];
        int i = d_inv[b * AA + a];
        int mg;
        if (__popcll(m) > 1) {
            float best = FLT_MAX; mg = 0;
            for (int g = 0; g < GG; g++) {
                float c = d_cost[(size_t)(b * GG + g) * SP + i];
                if (c < best) { best = c; mg = g; }
            }
        } else {
            mg = __ffsll((long long)m) - 1;
        }
        const float* L = labels + (b * GG + mg) * 5;
        int   mc = (int)L[0];
        float gxv = L[1], gyv = L[2], gwv = L[3], ghv = L[4];

        const float* o = outp + (size_t)(b * AA + a) * ROW;
        float bx = o[0], by = o[1], bw = o[2], bh = o[3];
        float tlx = fmaxf(bx - bw * 0.5f, gxv - gwv * 0.5f);
        float tly = fmaxf(by - bh * 0.5f, gyv - ghv * 0.5f);
        float brx = fminf(bx + bw * 0.5f, gxv + gwv * 0.5f);
        float bry = fminf(by + bh * 0.5f, gyv + ghv * 0.5f);
        float inter = (tlx < brx && tly < bry) ? (brx - tlx) * (bry - tly) : 0.0f;
        float pred_iou = inter / (bw * bh + gwv * ghv - inter);          // no eps
        float iou      = inter / (bw * bh + gwv * ghv - inter + 1e-16f); // eps
        v_iou = 1.0f - iou * iou;

        float cl = 0.0f;
#pragma unroll 8
        for (int c = 0; c < CC; c++) {
            float xl = o[5 + c];
            float t  = (c == mc) ? pred_iou : 0.0f;
            cl += fmaxf(xl, 0.0f) - xl * t + log1pf(expf(-fabsf(xl)));
        }
        v_cls = cl;

        float st = stA[a];
        float t0 = gxv / st - xsA[a];
        float t1 = gyv / st - ysA[a];
        float t2 = logf(gwv / st + 1e-8f);
        float t3 = logf(ghv / st + 1e-8f);
        const float* op = orig + (size_t)(b * AA + a) * 4;
        v_l1 = fabsf(op[0] - t0) + fabsf(op[1] - t1) +
               fabsf(op[2] - t2) + fabsf(op[3] - t3);
    }
    float r;
    r = blockSum(v_iou, s); if (threadIdx.x == 0) atomicAdd(&d_acc[0], (double)r);
    r = blockSum(v_cls, s); if (threadIdx.x == 0) atomicAdd(&d_acc[2], (double)r);
    r = blockSum(v_l1,  s); if (threadIdx.x == 0) atomicAdd(&d_acc[3], (double)r);
}

// ---------------- kernel 7: finalize ----------------
__global__ void k_final(float* out) {
    double nfg = d_acc[4];
    if (nfg < 1.0) nfg = 1.0;
    float liou = (float)(5.0 * d_acc[0] / nfg);
    float lobj = (float)(d_acc[1] / nfg);
    float lcls = (float)(d_acc[2] / nfg);
    float ll1  = (float)(d_acc[3] / nfg);
    out[0] = liou + lobj + lcls + ll1;
    out[1] = liou;
    out[2] = lobj;
    out[3] = lcls;
    out[4] = ll1;
    out[5] = (float)(d_acc[4] / (double)(BB * GG));
}

// ---------------- launch ----------------
extern "C" void kernel_launch(void* const* d_in, const int* in_sizes, int n_in,
                              void* d_out, int out_size) {
    const float* outputs = (const float*)d_in[0];
    const float* origin  = (const float*)d_in[1];
    const float* labels  = (const float*)d_in[2];
    const float* xs      = (const float*)d_in[3];
    const float* ys      = (const float*)d_in[4];
    const float* st      = (const float*)d_in[5];

    k_zero<<<1056, 256>>>();
    k_mark<<<30, 128>>>(labels);
    k_scan<<<BB, 256>>>();
    k_cost<<<dim3(SP / 128, BB), 128>>>(outputs, labels);
    k_select<<<BB * GG, 256>>>();
    k_obj<<<dim3((AA + 255) / 256, BB), 256>>>(outputs);
    k_fgloss<<<dim3(MM / 128, BB), 128>>>(outputs, origin, labels, xs, ys, st);
    k_final<<<1, 1>>>((float*)d_out);
}

// round 5
// speedup vs baseline: 1.2992x; 1.1616x over previous
#include <cuda_runtime.h>
#include <math.h>
#include <float.h>

#define BB 32
#define AA 8400
#define GG 40
#define CC 80
#define ROW 85
#define SP 1536      // max candidates per batch (row stride)
#define MM 512       // max matched anchors per batch

// ---------------- scratch (device globals; no allocation) ----------------
__device__ unsigned long long d_match[BB * AA];
__device__ unsigned long long d_inin [BB * AA];
__device__ int    d_fgidx[BB * SP];
__device__ int    d_inv  [BB * AA];
__device__ int    d_fgcnt[BB];
__device__ int    d_mcnt [BB];
__device__ int    d_midx [BB * MM];
__device__ float  d_cost[(size_t)BB * GG * SP];
__device__ float  d_iou [(size_t)BB * GG * SP];
__device__ double d_acc[6];
// compact per-candidate SoA
__device__ float  d_cx1[BB * SP], d_cy1[BB * SP], d_cx2[BB * SP], d_cy2[BB * SP];
__device__ float  d_car[BB * SP], d_cobj[BB * SP], d_suml[BB * SP];
__device__ unsigned long long d_cinin[BB * SP];

// ---------------- kernel 0: zero bitmasks + counters ----------------
__global__ void k_zero() {
    int stride = gridDim.x * blockDim.x;
    int t0 = blockIdx.x * blockDim.x + threadIdx.x;
    for (int i = t0; i < BB * AA; i += stride) {
        d_inin [i] = 0ull;
        d_match[i] = 0ull;
    }
    if (t0 < BB) d_mcnt[t0] = 0;
    if (t0 < 6)  d_acc[t0] = 0.0;
}

// ---------------- kernel 1: analytic center-region enumeration ----------------
__global__ void k_mark(const float* __restrict__ labels) {
    int t = blockIdx.x * blockDim.x + threadIdx.x;
    if (t >= BB * GG * 3) return;
    int sidx = t % 3;
    int g    = (t / 3) % GG;
    int b    = t / (3 * GG);
    const float* L = labels + (b * GG + g) * 5;
    float gxv = L[1], gyv = L[2];
    float s; int n, base;
    if (sidx == 0)      { s = 8.0f;  n = 80; base = 0;    }
    else if (sidx == 1) { s = 16.0f; n = 40; base = 6400; }
    else                { s = 32.0f; n = 20; base = 8000; }
    float r = 1.5f * s;
    int cx = (int)floorf(gxv / s);
    int cy = (int)floorf(gyv / s);
    for (int dy = -3; dy <= 2; dy++) {
        int ny = cy + dy;
        if (ny < 0 || ny >= n) continue;
        float yc = ((float)ny + 0.5f) * s;
        float dt = yc - (gyv - r);
        float db = (gyv + r) - yc;
        float my = fminf(dt, db);
        if (my <= 0.0f) continue;
        for (int dx = -3; dx <= 2; dx++) {
            int nx = cx + dx;
            if (nx < 0 || nx >= n) continue;
            float xc = ((float)nx + 0.5f) * s;
            float dl = xc - (gxv - r);
            float dr = (gxv + r) - xc;
            if (fminf(fminf(dl, dr), my) > 0.0f)
                atomicOr(&d_inin[b * AA + base + ny * n + nx], 1ull << g);
        }
    }
}

// ---------------- kernel 2: ordered compaction (warp-ballot scan) ----------------
__global__ void k_scan() {
    __shared__ int wcnt[8];
    int b = blockIdx.x;
    int tid = threadIdx.x, wid = tid >> 5, lane = tid & 31;
    const int CH = 1050;
    int base = wid * CH;
    int cnt = 0;
    for (int k = 0; k < 33; k++) {
        int a = base + k * 32 + lane;
        bool p = (a < base + CH) && (d_inin[b * AA + a] != 0ull);
        cnt += __popc(__ballot_sync(0xffffffffu, p));
    }
    if (lane == 0) wcnt[wid] = cnt;
    __syncthreads();
    int off = 0;
    for (int w2 = 0; w2 < wid; w2++) off += wcnt[w2];
    if (tid == 0) {
        int tot = 0;
        for (int w2 = 0; w2 < 8; w2++) tot += wcnt[w2];
        d_fgcnt[b] = tot < SP ? tot : SP;
    }
    int pos = off;
    for (int k = 0; k < 33; k++) {
        int a = base + k * 32 + lane;
        bool p = (a < base + CH) && (d_inin[b * AA + a] != 0ull);
        unsigned bal = __ballot_sync(0xffffffffu, p);
        int my = __popc(bal & ((1u << lane) - 1u));
        if (p && pos + my < SP) {
            d_fgidx[b * SP + pos + my] = a;
            d_inv  [b * AA + a]        = pos + my;
        }
        pos += __popc(bal);
    }
}

// ---------------- kernel 3a: candidate prep + suml (8 lanes / candidate) -----
// 128 threads = 4 warps; each warp covers 4 candidates -> 16 candidates/block.
__global__ void __launch_bounds__(128) k_prep(const float* __restrict__ outp) {
    int b   = blockIdx.y;
    int cnt = d_fgcnt[b];
    if (blockIdx.x * 16 >= cnt) return;              // whole-block uniform exit
    int tid  = threadIdx.x;
    int lane = tid & 31, warp = tid >> 5;
    int grp  = lane >> 3, sub = lane & 7;
    int i    = blockIdx.x * 16 + warp * 4 + grp;
    bool valid = (i < cnt);
    int ic = valid ? i : (cnt - 1);                  // clamp; full-warp shfl safe
    int a  = d_fgidx[b * SP + ic];
    const float* o = outp + (size_t)(b * AA + a) * ROW;
    float obj = o[4];
    // product of (1 - sqrt(cls*obj)) over this lane's 10 classes
    float prod = 1.0f;
#pragma unroll
    for (int c = 0; c < 10; c++) {
        float x = o[5 + sub * 10 + c] * obj;
        prod *= (1.0f - x * rsqrtf(x));
    }
    float l = __logf(prod);
    l += __shfl_xor_sync(0xffffffffu, l, 1);
    l += __shfl_xor_sync(0xffffffffu, l, 2);
    l += __shfl_xor_sync(0xffffffffu, l, 4);
    if (sub == 0 && valid) {
        float bx = o[0], by = o[1], bw = o[2], bh = o[3];
        int idx = b * SP + i;
        d_cx1[idx] = bx - bw * 0.5f; d_cy1[idx] = by - bh * 0.5f;
        d_cx2[idx] = bx + bw * 0.5f; d_cy2[idx] = by + bh * 0.5f;
        d_car[idx] = bw * bh;
        d_cobj[idx] = obj;
        d_suml[idx] = l;
        d_cinin[idx] = d_inin[b * AA + a];
    }
}

// ---------------- kernel 3b: pairwise iou + cost (thread per (b,g,i)) --------
__global__ void __launch_bounds__(128) k_pair(const float* __restrict__ outp,
                                              const float* __restrict__ labels) {
    int bg = blockIdx.y;
    int b = bg / GG, g = bg % GG;
    int cnt = d_fgcnt[b];
    int i = blockIdx.x * 128 + threadIdx.x;
    if (i >= cnt) return;
    const float* L = labels + (b * GG + g) * 5;      // uniform: broadcast loads
    int   gc  = (int)L[0];
    float gxv = L[1], gyv = L[2], gwv = L[3], ghv = L[4];
    float qx1 = gxv - gwv * 0.5f, qx2 = gxv + gwv * 0.5f;
    float qy1 = gyv - ghv * 0.5f, qy2 = gyv + ghv * 0.5f;
    float qar = gwv * ghv;

    int idx = b * SP + i;
    float w = fminf(d_cx2[idx], qx2) - fmaxf(d_cx1[idx], qx1);
    float h = fminf(d_cy2[idx], qy2) - fmaxf(d_cy1[idx], qy1);
    float inter = fmaxf(w, 0.0f) * fmaxf(h, 0.0f);
    float den = d_car[idx] + qar - inter;
    // FMA-pipe reciprocal (bit-trick + 2 Newton); den >= 1 always here
    float y = __uint_as_float(0x7EF311C3u - __float_as_uint(den));
    y = y * (2.0f - den * y);
    y = y * (2.0f - den * y);
    float iou = inter * y;
    size_t off = (size_t)bg * SP + i;
    d_iou[off] = iou;
    float cost = FLT_MAX;
    if ((d_cinin[idx] >> g) & 1ull) {
        int a = d_fgidx[b * SP + i];
        float xg = outp[(size_t)(b * AA + a) * ROW + 5 + gc] * d_cobj[idx];
        float pg = xg * rsqrtf(xg);
        cost = -d_suml[idx] - (0.5f * __logf(xg) - __logf(1.0f - pg))
               - 3.0f * __logf(iou + 1e-8f);
    }
    d_cost[off] = cost;
}

// ---------------- kernel 4: block-per-(b,g) dynamic_k + stable top-k ----------
__global__ void __launch_bounds__(256) k_select() {
    __shared__ unsigned long long swp[8];
    __shared__ unsigned long long sbest;
    int bg = blockIdx.x;
    int b  = bg / GG;
    int tid = threadIdx.x, lane = tid & 31, wid = tid >> 5;
    int N = d_fgcnt[b];
    const float* irow = d_iou  + (size_t)bg * SP;
    const float* crow = d_cost + (size_t)bg * SP;

    unsigned kiou[6], kcst[6];
#pragma unroll
    for (int j = 0; j < 6; j++) {
        int i = tid + j * 256;
        bool v = (i < N);
        kiou[j] = v ? __float_as_uint(irow[i]) : 0u;
        unsigned cb = v ? __float_as_uint(crow[i]) : 0x7F800000u;
        kcst[j] = (cb & 0x80000000u) ? ~cb : (cb | 0x80000000u);
    }

    // phase A: sum of top-10 iou values
    float sum = 0.0f;
    unsigned long long prev = ~0ull;
    for (int t = 0; t < 10; t++) {
        unsigned long long best = 0ull;
#pragma unroll
        for (int j = 0; j < 6; j++) {
            unsigned long long key =
                ((unsigned long long)kiou[j] << 32) | (unsigned)(tid + j * 256);
            if (key < prev && key > best) best = key;
        }
#pragma unroll
        for (int o = 16; o > 0; o >>= 1) {
            unsigned long long oth = __shfl_xor_sync(0xffffffffu, best, o);
            if (oth > best) best = oth;
        }
        if (lane == 0) swp[wid] = best;
        __syncthreads();
        if (tid == 0) {
            unsigned long long m = swp[0];
#pragma unroll
            for (int w2 = 1; w2 < 8; w2++) if (swp[w2] > m) m = swp[w2];
            sbest = m;
        }
        __syncthreads();
        prev = sbest;
        sum += __uint_as_float((unsigned)(prev >> 32));
    }
    int k = (int)sum;
    if (k < 1)  k = 1;
    if (k > 10) k = 10;

    // phase B: k smallest (cost, idx) — stable argsort tie-break by index
    prev = 0ull;
    for (int t = 0; t < k; t++) {
        unsigned long long best = ~0ull;
#pragma unroll
        for (int j = 0; j < 6; j++) {
            unsigned long long key =
                ((unsigned long long)kcst[j] << 32) | (unsigned)(tid + j * 256);
            if (key > prev && key < best) best = key;
        }
#pragma unroll
        for (int o = 16; o > 0; o >>= 1) {
            unsigned long long oth = __shfl_xor_sync(0xffffffffu, best, o);
            if (oth < best) best = oth;
        }
        if (lane == 0) swp[wid] = best;
        __syncthreads();
        if (tid == 0) {
            unsigned long long m = swp[0];
#pragma unroll
            for (int w2 = 1; w2 < 8; w2++) if (swp[w2] < m) m = swp[w2];
            sbest = m;
            int i = (int)(unsigned)(m & 0xFFFFFFFFull);
            if (m != ~0ull && i < N) {
                int g = bg - b * GG;
                int a = d_fgidx[b * SP + i];
                atomicOr(&d_match[b * AA + a], 1ull << g);
            }
        }
        __syncthreads();
        prev = sbest;
    }
}

// ---------------- block reduction helper ----------------
__device__ __forceinline__ float blockSum(float v, float* s) {
    int tid = threadIdx.x;
#pragma unroll
    for (int o = 16; o > 0; o >>= 1) v += __shfl_xor_sync(0xffffffffu, v, o);
    if ((tid & 31) == 0) s[tid >> 5] = v;
    __syncthreads();
    float r = 0.0f;
    if (tid < (blockDim.x >> 5)) r = s[tid];
#pragma unroll
    for (int o = 4; o > 0; o >>= 1) r += __shfl_xor_sync(0xffffffffu, r, o);
    __syncthreads();
    return r;   // valid in thread 0
}

// ---------------- kernel 5: obj BCE over all anchors + matched compaction ----
__global__ void k_obj(const float* __restrict__ outp) {
    __shared__ float s[8];
    int b = blockIdx.y;
    int a = blockIdx.x * blockDim.x + threadIdx.x;
    float vo = 0.0f, vf = 0.0f;
    if (a < AA) {
        unsigned long long m = d_match[b * AA + a];
        float x = outp[(size_t)(b * AA + a) * ROW + 4];
        float fg = m ? 1.0f : 0.0f;
        vo = fmaxf(x, 0.0f) - x * fg + __logf(1.0f + __expf(-fabsf(x)));
        if (m) {
            vf = 1.0f;
            int pos = atomicAdd(&d_mcnt[b], 1);
            if (pos < MM) d_midx[b * MM + pos] = a;
        }
    }
    float r;
    r = blockSum(vo, s); if (threadIdx.x == 0) atomicAdd(&d_acc[1], (double)r);
    r = blockSum(vf, s); if (threadIdx.x == 0) atomicAdd(&d_acc[4], (double)r);
}

// ---------------- kernel 6: heavy losses on matched anchors only -------------
__global__ void __launch_bounds__(128) k_fgloss(const float* __restrict__ outp,
                                                const float* __restrict__ orig,
                                                const float* __restrict__ labels,
                                                const float* __restrict__ xsA,
                                                const float* __restrict__ ysA,
                                                const float* __restrict__ stA) {
    __shared__ float s[8];
    int b = blockIdx.y;
    int j = blockIdx.x * 128 + threadIdx.x;
    float v_iou = 0.0f, v_cls = 0.0f, v_l1 = 0.0f;
    int mc2 = d_mcnt[b]; if (mc2 > MM) mc2 = MM;
    if (j < mc2) {
        int a = d_midx[b * MM + j];
        unsigned long long m = d_match[b * AA + a];
        int i = d_inv[b * AA + a];
        int mg;
        if (__popcll(m) > 1) {
            float best = FLT_MAX; mg = 0;
            for (int g = 0; g < GG; g++) {
                float c = d_cost[(size_t)(b * GG + g) * SP + i];
                if (c < best) { best = c; mg = g; }
            }
        } else {
            mg = __ffsll((long long)m) - 1;
        }
        const float* L = labels + (b * GG + mg) * 5;
        int   mc = (int)L[0];
        float gxv = L[1], gyv = L[2], gwv = L[3], ghv = L[4];

        const float* o = outp + (size_t)(b * AA + a) * ROW;
        float bx = o[0], by = o[1], bw = o[2], bh = o[3];
        float tlx = fmaxf(bx - bw * 0.5f, gxv - gwv * 0.5f);
        float tly = fmaxf(by - bh * 0.5f, gyv - ghv * 0.5f);
        float brx = fminf(bx + bw * 0.5f, gxv + gwv * 0.5f);
        float bry = fminf(by + bh * 0.5f, gyv + ghv * 0.5f);
        float inter = (tlx < brx && tly < bry) ? (brx - tlx) * (bry - tly) : 0.0f;
        float pred_iou = inter / (bw * bh + gwv * ghv - inter);
        float iou      = inter / (bw * bh + gwv * ghv - inter + 1e-16f);
        v_iou = 1.0f - iou * iou;

        float cl = 0.0f;
#pragma unroll 8
        for (int c = 0; c < CC; c++) {
            float xl = o[5 + c];
            float t  = (c == mc) ? pred_iou : 0.0f;
            cl += fmaxf(xl, 0.0f) - xl * t + log1pf(expf(-fabsf(xl)));
        }
        v_cls = cl;

        float st = stA[a];
        float t0 = gxv / st - xsA[a];
        float t1 = gyv / st - ysA[a];
        float t2 = logf(gwv / st + 1e-8f);
        float t3 = logf(ghv / st + 1e-8f);
        const float* op = orig + (size_t)(b * AA + a) * 4;
        v_l1 = fabsf(op[0] - t0) + fabsf(op[1] - t1) +
               fabsf(op[2] - t2) + fabsf(op[3] - t3);
    }
    float r;
    r = blockSum(v_iou, s); if (threadIdx.x == 0) atomicAdd(&d_acc[0], (double)r);
    r = blockSum(v_cls, s); if (threadIdx.x == 0) atomicAdd(&d_acc[2], (double)r);
    r = blockSum(v_l1,  s); if (threadIdx.x == 0) atomicAdd(&d_acc[3], (double)r);
}

// ---------------- kernel 7: finalize ----------------
__global__ void k_final(float* out) {
    double nfg = d_acc[4];
    if (nfg < 1.0) nfg = 1.0;
    float liou = (float)(5.0 * d_acc[0] / nfg);
    float lobj = (float)(d_acc[1] / nfg);
    float lcls = (float)(d_acc[2] / nfg);
    float ll1  = (float)(d_acc[3] / nfg);
    out[0] = liou + lobj + lcls + ll1;
    out[1] = liou;
    out[2] = lobj;
    out[3] = lcls;
    out[4] = ll1;
    out[5] = (float)(d_acc[4] / (double)(BB * GG));
}

// ---------------- launch ----------------
extern "C" void kernel_launch(void* const* d_in, const int* in_sizes, int n_in,
                              void* d_out, int out_size) {
    const float* outputs = (const float*)d_in[0];
    const float* origin  = (const float*)d_in[1];
    const float* labels  = (const float*)d_in[2];
    const float* xs      = (const float*)d_in[3];
    const float* ys      = (const float*)d_in[4];
    const float* st      = (const float*)d_in[5];

    k_zero<<<1056, 256>>>();
    k_mark<<<30, 128>>>(labels);
    k_scan<<<BB, 256>>>();
    k_prep<<<dim3(SP / 16, BB), 128>>>(outputs);
    k_pair<<<dim3(SP / 128, BB * GG), 128>>>(outputs, labels);
    k_select<<<BB * GG, 256>>>();
    k_obj<<<dim3((AA + 255) / 256, BB), 256>>>(outputs);
    k_fgloss<<<dim3(MM / 128, BB), 128>>>(outputs, origin, labels, xs, ys, st);
    k_final<<<1, 1>>>((float*)d_out);
}